// round 8
// baseline (speedup 1.0000x reference)
#include <cuda_runtime.h>
#include <cuda_bf16.h>
#include <cstdint>
#include <cstddef>

#define RELS   16
#define INDIM  128
#define HDIM   128
#define ODIM   64
#define NMAX   50000
#define EMAX   800000

// ---------------------------------------------------------------------------
// Scratch (__device__ globals; allocation-free rule)
// ---------------------------------------------------------------------------
__device__ float g_h[(size_t)NMAX * HDIM];                  // [N,128] ~25.6MB (L2)
__device__ __nv_bfloat16 g_w1hi[RELS * 128 * 128];          // W1^T [r][n][k]
__device__ __nv_bfloat16 g_w1lo[RELS * 128 * 128];
__device__ __nv_bfloat16 g_w2hi[RELS * 64 * 128];           // W2^T [r][n][k]
__device__ __nv_bfloat16 g_w2lo[RELS * 64 * 128];
__device__ int   g_hist[RELS];
__device__ int   g_reloff[RELS + 1];
__device__ int   g_blkoff[RELS + 1];
__device__ int   g_cursor[RELS];
__device__ int   g_srcp[EMAX];
__device__ int   g_dstp[EMAX];
__device__ float g_normp[EMAX];

// ---------------------------------------------------------------------------
// Helpers (arch-agnostic PTX: ldmatrix sm_75+, mma.bf16 sm_80+)
// ---------------------------------------------------------------------------
__device__ __forceinline__ uint32_t smem_u32(const void* p) {
    uint32_t a;
    asm("{ .reg .u64 t; cvta.to.shared.u64 t, %1; cvt.u32.u64 %0, t; }"
        : "=r"(a) : "l"(p));
    return a;
}
#define SWZ128(o) ((o) ^ (((o) >> 3) & 0x70))

__device__ __forceinline__ void ldsm4(uint32_t* r, uint32_t addr) {
    asm volatile("ldmatrix.sync.aligned.m8n8.x4.shared.b16 {%0,%1,%2,%3}, [%4];"
                 : "=r"(r[0]), "=r"(r[1]), "=r"(r[2]), "=r"(r[3]) : "r"(addr));
}
__device__ __forceinline__ void mma16816(float* d, const uint32_t* a, const uint32_t* b) {
    asm volatile("mma.sync.aligned.m16n8k16.row.col.f32.bf16.bf16.f32 "
                 "{%0,%1,%2,%3}, {%4,%5,%6,%7}, {%8,%9}, {%0,%1,%2,%3};"
                 : "+f"(d[0]), "+f"(d[1]), "+f"(d[2]), "+f"(d[3])
                 : "r"(a[0]), "r"(a[1]), "r"(a[2]), "r"(a[3]), "r"(b[0]), "r"(b[1]));
}
__device__ __forceinline__ uint32_t pack_bf16x2(float a, float b) {
    __nv_bfloat16 ha = __float2bfloat16(a), hb = __float2bfloat16(b);
    return (uint32_t)__bfloat16_as_ushort(ha) |
           ((uint32_t)__bfloat16_as_ushort(hb) << 16);
}

// ---------------------------------------------------------------------------
// Combined weight split (W1 & W2 -> transposed hi/lo bf16) + hist zero.
// ---------------------------------------------------------------------------
__global__ void splitWall(const float* __restrict__ W1, const float* __restrict__ W2,
                          __nv_bfloat16* __restrict__ w1hi, __nv_bfloat16* __restrict__ w1lo,
                          __nv_bfloat16* __restrict__ w2hi, __nv_bfloat16* __restrict__ w2lo) {
    int i = blockIdx.x * blockDim.x + threadIdx.x;
    int stride = gridDim.x * blockDim.x;
    if (i < RELS) g_hist[i] = 0;
    const int t1 = RELS * 128 * 128;
    for (int o = i; o < t1; o += stride) {
        int r = o / (128 * 128);
        int rem = o - r * 128 * 128;
        int n = rem >> 7, k = rem & 127;
        float v = W1[((size_t)r * 128 + k) * 128 + n];
        __nv_bfloat16 h = __float2bfloat16(v);
        w1hi[o] = h;
        w1lo[o] = __float2bfloat16(v - __bfloat162float(h));
    }
    const int t2 = RELS * 64 * 128;
    for (int o = i; o < t2; o += stride) {
        int r = o / (64 * 128);
        int rem = o - r * 64 * 128;
        int n = rem >> 7, k = rem & 127;
        float v = W2[((size_t)r * 128 + k) * 64 + n];
        __nv_bfloat16 h = __float2bfloat16(v);
        w2hi[o] = h;
        w2lo[o] = __float2bfloat16(v - __bfloat162float(h));
    }
}

// ---------------------------------------------------------------------------
// Edge bucket sort by etype: hist -> scan -> permute
// ---------------------------------------------------------------------------
__global__ void histk(const int* __restrict__ ety, int E) {
    __shared__ int sh[RELS];
    if (threadIdx.x < RELS) sh[threadIdx.x] = 0;
    __syncthreads();
    int e = blockIdx.x * blockDim.x + threadIdx.x;
    if (e < E) atomicAdd(&sh[ety[e]], 1);
    __syncthreads();
    if (threadIdx.x < RELS) atomicAdd(&g_hist[threadIdx.x], sh[threadIdx.x]);
}
__global__ void scank() {
    int off = 0, boff = 0;
    for (int r = 0; r < RELS; r++) {
        g_reloff[r] = off; g_blkoff[r] = boff; g_cursor[r] = off;
        int c = g_hist[r];
        off += c; boff += (c + 127) / 128;
    }
    g_reloff[RELS] = off; g_blkoff[RELS] = boff;
}
__global__ void permutek(const int* __restrict__ src, const int* __restrict__ dst,
                         const int* __restrict__ ety, const float* __restrict__ norm, int E) {
    __shared__ int sh[RELS], sbase[RELS];
    if (threadIdx.x < RELS) sh[threadIdx.x] = 0;
    __syncthreads();
    int e = blockIdx.x * blockDim.x + threadIdx.x;
    int r = 0, lr = 0;
    if (e < E) { r = ety[e]; lr = atomicAdd(&sh[r], 1); }
    __syncthreads();
    if (threadIdx.x < RELS) sbase[threadIdx.x] = atomicAdd(&g_cursor[threadIdx.x], sh[threadIdx.x]);
    __syncthreads();
    if (e < E) {
        int pos = sbase[r] + lr;
        g_srcp[pos] = src[e];
        g_dstp[pos] = dst[e];
        g_normp[pos] = norm[e];
    }
}

// ---------------------------------------------------------------------------
// Zero both accumulators in one launch.
// ---------------------------------------------------------------------------
__global__ void zeroall(float4* __restrict__ h4, int n4h, float4* __restrict__ o4, int n4o) {
    int i = blockIdx.x * blockDim.x + threadIdx.x;
    if (i < n4h) h4[i] = make_float4(0.f, 0.f, 0.f, 0.f);
    else if (i - n4h < n4o) o4[i - n4h] = make_float4(0.f, 0.f, 0.f, 0.f);
}

// ---------------------------------------------------------------------------
// Fused gather + tensor-core GEMM + scatter. 96KB smem -> 2 CTAs/SM.
// CTA = 128 edges x 64 output cols (layer1 uses 2 half-CTAs per edge tile).
// 3-product bf16 split (hi*hi + hi*lo + lo*hi), fp32 accumulate.
// ---------------------------------------------------------------------------
template <int COLSFULL, bool RELU>
__global__ __launch_bounds__(256, 2)
void rgcn_fused64(const float* __restrict__ A,
                  const __nv_bfloat16* __restrict__ Whi, const __nv_bfloat16* __restrict__ Wlo,
                  float* __restrict__ Out) {
    extern __shared__ char smem[];
    constexpr int HALVES = COLSFULL / 64;
    constexpr int ATILE = 128 * 128;      // bytes per K-subtile of A (128r x 64k x 2B)
    constexpr int BTILE = 64 * 128;       // bytes per K-subtile of B (64n x 64k x 2B)
    constexpr int A_HI = 0;
    constexpr int A_LO = 2 * ATILE;       // 32KB
    constexpr int B_HI = 4 * ATILE;       // 64KB
    constexpr int B_LO = B_HI + 2 * BTILE;// 80KB   (total 96KB)
    constexpr int STR = 68;               // staging stride (floats)

    float* stag = (float*)smem;           // reuses A/B after MMA
    const uint32_t sb = smem_u32(smem);
    const int tid = threadIdx.x;
    const int wid = tid >> 5;
    const int lane = tid & 31;

    const int bid = blockIdx.x;
    const int tile = bid / HALVES;
    const int half = bid % HALVES;
    if (tile >= __ldg(&g_blkoff[RELS])) return;
    int r = 0;
#pragma unroll
    for (int i = 0; i < RELS; i++)
        if (tile >= __ldg(&g_blkoff[i + 1])) r = i + 1;
    const int e0 = __ldg(&g_reloff[r]) + (tile - __ldg(&g_blkoff[r])) * 128;
    const int nE = min(128, __ldg(&g_reloff[r + 1]) - e0);

    // ---- gather A rows (fp32 -> hi/lo bf16), swizzled; starts immediately ----
    {
        const int u = tid & 15;
        const int r0 = tid >> 4;
#pragma unroll
        for (int it = 0; it < 8; it++) {
            int row = r0 + it * 16;
            uint32_t so = (u >> 3) * ATILE + SWZ128(row * 128 + (u & 7) * 16);
            uint32_t hi[4] = {0, 0, 0, 0}, lo[4] = {0, 0, 0, 0};
            if (row < nE) {
                int s = __ldg(&g_srcp[e0 + row]);
                const float* ap = A + (size_t)s * 128 + u * 8;
                float4 v0 = __ldg((const float4*)ap);
                float4 v1 = __ldg((const float4*)(ap + 4));
                float vs[8] = {v0.x, v0.y, v0.z, v0.w, v1.x, v1.y, v1.z, v1.w};
                if (RELU) {
#pragma unroll
                    for (int j = 0; j < 8; j++) vs[j] = fmaxf(vs[j], 0.f);
                }
#pragma unroll
                for (int j = 0; j < 4; j++) {
                    float a = vs[2 * j], b = vs[2 * j + 1];
                    __nv_bfloat16 ha = __float2bfloat16(a), hb = __float2bfloat16(b);
                    hi[j] = (uint32_t)__bfloat16_as_ushort(ha) |
                            ((uint32_t)__bfloat16_as_ushort(hb) << 16);
                    lo[j] = pack_bf16x2(a - __bfloat162float(ha), b - __bfloat162float(hb));
                }
            }
            *(uint4*)(smem + A_HI + so) = make_uint4(hi[0], hi[1], hi[2], hi[3]);
            *(uint4*)(smem + A_LO + so) = make_uint4(lo[0], lo[1], lo[2], lo[3]);
        }
    }
    // ---- load W_r half (pre-split hi/lo), swizzled ----
    for (int i = tid; i < 64 * 16; i += 256) {
        int n = i >> 4, u = i & 15;
        uint32_t so = (u >> 3) * BTILE + SWZ128(n * 128 + (u & 7) * 16);
        const size_t gi = ((size_t)r * COLSFULL + half * 64 + n) * 128 + u * 8;
        *(uint4*)(smem + B_HI + so) = *(const uint4*)(Whi + gi);
        *(uint4*)(smem + B_LO + so) = *(const uint4*)(Wlo + gi);
    }
    __syncthreads();

    // ---- MMA: warp = 32 rows x 32 cols ----
    const int wm = wid & 3;       // row group
    const int wn = wid >> 2;      // col group (0/1)
    float acc[2][4][4];
#pragma unroll
    for (int mf = 0; mf < 2; mf++)
#pragma unroll
        for (int nf = 0; nf < 4; nf++)
#pragma unroll
            for (int j = 0; j < 4; j++) acc[mf][nf][j] = 0.f;

    const int hf = lane >> 4;
    const int sr = lane & 15;
    const int a_off[3] = {A_HI, A_HI, A_LO};
    const int b_off[3] = {B_HI, B_LO, B_HI};

#pragma unroll
    for (int p = 0; p < 3; p++) {
        const uint32_t abase = sb + a_off[p];
        const uint32_t bbase = sb + b_off[p];
#pragma unroll
        for (int ks = 0; ks < 8; ks++) {
            const int kt = ks >> 2;
            const int kb = (ks & 3) * 32;
            uint32_t a[2][4];
#pragma unroll
            for (int mf = 0; mf < 2; mf++) {
                int row = wm * 32 + mf * 16 + sr;
                ldsm4(a[mf], abase + kt * ATILE + SWZ128(row * 128 + kb + hf * 16));
            }
            uint32_t b[4][2];
#pragma unroll
            for (int nq = 0; nq < 2; nq++) {
                int n = wn * 32 + nq * 16 + sr;
                uint32_t t[4];
                ldsm4(t, bbase + kt * BTILE + SWZ128(n * 128 + kb + hf * 16));
                b[nq * 2][0] = t[0]; b[nq * 2][1] = t[2];
                b[nq * 2 + 1][0] = t[1]; b[nq * 2 + 1][1] = t[3];
            }
#pragma unroll
            for (int mf = 0; mf < 2; mf++)
#pragma unroll
                for (int nf = 0; nf < 4; nf++)
                    mma16816(acc[mf][nf], a[mf], b[nf]);
        }
    }
    __syncthreads();   // A/B tiles dead; reuse as staging

    // ---- stage fp32 result ----
    const int mrow = lane >> 2;
    const int mcol = (lane & 3) * 2;
#pragma unroll
    for (int mf = 0; mf < 2; mf++)
#pragma unroll
        for (int rr = 0; rr < 2; rr++) {
            int lrow = wm * 32 + mf * 16 + mrow + rr * 8;
            float* o = stag + lrow * STR + wn * 32 + mcol;
#pragma unroll
            for (int nf = 0; nf < 4; nf++)
                *(float2*)(o + nf * 8) =
                    make_float2(acc[mf][nf][rr * 2], acc[mf][nf][rr * 2 + 1]);
        }
    __syncthreads();

    // ---- scale by norm, red.add.v4 into Out[dst] ----
#pragma unroll
    for (int it = 0; it < 8; it++) {
        int idx = tid + it * 256;
        int row = idx >> 4, c4 = idx & 15;
        if (row < nE) {
            float nm = __ldg(&g_normp[e0 + row]);
            int d = __ldg(&g_dstp[e0 + row]);
            float4 v = *(float4*)(stag + row * STR + c4 * 4);
            v.x *= nm; v.y *= nm; v.z *= nm; v.w *= nm;
            float* o = Out + (size_t)d * COLSFULL + half * 64 + c4 * 4;
            asm volatile("red.global.add.v4.f32 [%0], {%1, %2, %3, %4};"
                         :: "l"(o), "f"(v.x), "f"(v.y), "f"(v.z), "f"(v.w) : "memory");
        }
    }
}

// ---------------------------------------------------------------------------
// Launch. Order keeps the layer-1 fused kernel as launch #6 (ncu -s 5 -c 1).
// ---------------------------------------------------------------------------
extern "C" void kernel_launch(void* const* d_in, const int* in_sizes, int n_in,
                              void* d_out, int out_size) {
    const float* feat = (const float*)d_in[0];
    const float* norm = (const float*)d_in[1];
    const float* W1   = (const float*)d_in[2];
    const float* W2   = (const float*)d_in[3];
    const int*   src  = (const int*)d_in[4];
    const int*   dst  = (const int*)d_in[5];
    const int*   ety  = (const int*)d_in[6];
    float* out = (float*)d_out;

    const int N = in_sizes[0] / INDIM;   // 50000
    const int E = in_sizes[4];           // 800000

    float* hp;
    __nv_bfloat16 *w1hip, *w1lop, *w2hip, *w2lop;
    cudaGetSymbolAddress((void**)&hp,    g_h);
    cudaGetSymbolAddress((void**)&w1hip, g_w1hi);
    cudaGetSymbolAddress((void**)&w1lop, g_w1lo);
    cudaGetSymbolAddress((void**)&w2hip, g_w2hi);
    cudaGetSymbolAddress((void**)&w2lop, g_w2lo);

    constexpr int SM = 4 * 128 * 128 + 4 * 64 * 128;  // 98304 B
    cudaFuncSetAttribute(rgcn_fused64<128, false>,
                         cudaFuncAttributeMaxDynamicSharedMemorySize, SM);
    cudaFuncSetAttribute(rgcn_fused64<64, true>,
                         cudaFuncAttributeMaxDynamicSharedMemorySize, SM);

    // 1. weight split (+hist zero)
    splitWall<<<1024, 256>>>(W1, W2, w1hip, w1lop, w2hip, w2lop);
    // 2-4. edge bucket sort
    const int eb = (E + 255) / 256;
    histk<<<eb, 256>>>(ety, E);
    scank<<<1, 1>>>();
    permutek<<<eb, 256>>>(src, dst, ety, norm, E);
    // 5. zero accumulators
    {
        int n4h = N * HDIM / 4, n4o = N * ODIM / 4;
        zeroall<<<(n4h + n4o + 255) / 256, 256>>>((float4*)hp, n4h, (float4*)out, n4o);
    }
    // 6. layer 1 (two half-CTAs per edge tile)
    const int tiles = (E + 127) / 128 + RELS;
    rgcn_fused64<128, false><<<tiles * 2, 256, SM>>>(feat, w1hip, w1lop, hp);
    // 7. layer 2
    rgcn_fused64<64, true><<<tiles, 256, SM>>>(hp, w2hip, w2lop, out);
}

// round 10
// speedup vs baseline: 1.0502x; 1.0502x over previous
#include <cuda_runtime.h>
#include <cuda_bf16.h>
#include <cstdint>
#include <cstddef>

#define RELS   16
#define INDIM  128
#define HDIM   128
#define ODIM   64
#define NMAX   50000
#define EMAX   800000

// ---------------------------------------------------------------------------
// Scratch (__device__ globals; allocation-free rule)
// ---------------------------------------------------------------------------
__device__ float g_h[(size_t)NMAX * HDIM];                  // [N,128] ~25.6MB (L2)
__device__ __nv_bfloat16 g_w1hi[RELS * 128 * 128];          // W1^T [r][n][k]
__device__ __nv_bfloat16 g_w1lo[RELS * 128 * 128];
__device__ __nv_bfloat16 g_w2hi[RELS * 64 * 128];           // W2^T [r][n][k]
__device__ __nv_bfloat16 g_w2lo[RELS * 64 * 128];
__device__ int   g_hist[RELS];
__device__ int   g_reloff[RELS + 1];
__device__ int   g_blkoff[RELS + 1];
__device__ int   g_cursor[RELS];
__device__ int   g_srcp[EMAX];
__device__ int   g_dstp[EMAX];
__device__ float g_normp[EMAX];

// ---------------------------------------------------------------------------
// Helpers (arch-agnostic PTX: ldmatrix sm_75+, mma.bf16 sm_80+)
// ---------------------------------------------------------------------------
__device__ __forceinline__ uint32_t smem_u32(const void* p) {
    uint32_t a;
    asm("{ .reg .u64 t; cvta.to.shared.u64 t, %1; cvt.u32.u64 %0, t; }"
        : "=r"(a) : "l"(p));
    return a;
}
#define SWZ128(o) ((o) ^ (((o) >> 3) & 0x70))

__device__ __forceinline__ void ldsm4(uint32_t* r, uint32_t addr) {
    asm volatile("ldmatrix.sync.aligned.m8n8.x4.shared.b16 {%0,%1,%2,%3}, [%4];"
                 : "=r"(r[0]), "=r"(r[1]), "=r"(r[2]), "=r"(r[3]) : "r"(addr));
}
__device__ __forceinline__ void mma16816(float* d, const uint32_t* a, const uint32_t* b) {
    asm volatile("mma.sync.aligned.m16n8k16.row.col.f32.bf16.bf16.f32 "
                 "{%0,%1,%2,%3}, {%4,%5,%6,%7}, {%8,%9}, {%0,%1,%2,%3};"
                 : "+f"(d[0]), "+f"(d[1]), "+f"(d[2]), "+f"(d[3])
                 : "r"(a[0]), "r"(a[1]), "r"(a[2]), "r"(a[3]), "r"(b[0]), "r"(b[1]));
}
__device__ __forceinline__ uint32_t pack_bf16x2(float a, float b) {
    __nv_bfloat16 ha = __float2bfloat16(a), hb = __float2bfloat16(b);
    return (uint32_t)__bfloat16_as_ushort(ha) |
           ((uint32_t)__bfloat16_as_ushort(hb) << 16);
}

// Map tile index -> (relation, edge base, edge count)
__device__ __forceinline__ void tmap(int tile, int& r, int& e0, int& nE) {
    int rr = 0;
#pragma unroll
    for (int i = 0; i < RELS; i++)
        if (tile >= __ldg(&g_blkoff[i + 1])) rr = i + 1;
    r = rr;
    e0 = __ldg(&g_reloff[rr]) + (tile - __ldg(&g_blkoff[rr])) * 128;
    nE = min(128, __ldg(&g_reloff[rr + 1]) - e0);
}

// Convert 8 fp32 -> hi/lo bf16 pairs, store swizzled into A buffer at byte off.
template <bool RELU>
__device__ __forceinline__ void cvt_store(char* smem, uint32_t bufo, int row, int ucol,
                                          float4 v0, float4 v1) {
    uint32_t so = (uint32_t)(ucol >> 3) * 16384u + SWZ128((uint32_t)(row * 128 + (ucol & 7) * 16));
    float vs[8] = {v0.x, v0.y, v0.z, v0.w, v1.x, v1.y, v1.z, v1.w};
    if (RELU) {
#pragma unroll
        for (int j = 0; j < 8; j++) vs[j] = fmaxf(vs[j], 0.f);
    }
    uint32_t hi[4], lo[4];
#pragma unroll
    for (int j = 0; j < 4; j++) {
        float a = vs[2 * j], b = vs[2 * j + 1];
        __nv_bfloat16 ha = __float2bfloat16(a), hb = __float2bfloat16(b);
        hi[j] = (uint32_t)__bfloat16_as_ushort(ha) |
                ((uint32_t)__bfloat16_as_ushort(hb) << 16);
        lo[j] = pack_bf16x2(a - __bfloat162float(ha), b - __bfloat162float(hb));
    }
    *(uint4*)(smem + bufo + so) = make_uint4(hi[0], hi[1], hi[2], hi[3]);
    *(uint4*)(smem + bufo + 32768 + so) = make_uint4(lo[0], lo[1], lo[2], lo[3]);
}

// ---------------------------------------------------------------------------
// Combined weight split (W1 & W2 -> transposed hi/lo bf16) + hist zero.
// ---------------------------------------------------------------------------
__global__ void splitWall(const float* __restrict__ W1, const float* __restrict__ W2,
                          __nv_bfloat16* __restrict__ w1hi, __nv_bfloat16* __restrict__ w1lo,
                          __nv_bfloat16* __restrict__ w2hi, __nv_bfloat16* __restrict__ w2lo) {
    int i = blockIdx.x * blockDim.x + threadIdx.x;
    int stride = gridDim.x * blockDim.x;
    if (i < RELS) g_hist[i] = 0;
    const int t1 = RELS * 128 * 128;
    for (int o = i; o < t1; o += stride) {
        int r = o / (128 * 128);
        int rem = o - r * 128 * 128;
        int n = rem >> 7, k = rem & 127;
        float v = W1[((size_t)r * 128 + k) * 128 + n];
        __nv_bfloat16 h = __float2bfloat16(v);
        w1hi[o] = h;
        w1lo[o] = __float2bfloat16(v - __bfloat162float(h));
    }
    const int t2 = RELS * 64 * 128;
    for (int o = i; o < t2; o += stride) {
        int r = o / (64 * 128);
        int rem = o - r * 64 * 128;
        int n = rem >> 7, k = rem & 127;
        float v = W2[((size_t)r * 128 + k) * 64 + n];
        __nv_bfloat16 h = __float2bfloat16(v);
        w2hi[o] = h;
        w2lo[o] = __float2bfloat16(v - __bfloat162float(h));
    }
}

// ---------------------------------------------------------------------------
// Edge bucket sort by etype: hist -> scan -> permute
// ---------------------------------------------------------------------------
__global__ void histk(const int* __restrict__ ety, int E) {
    __shared__ int sh[RELS];
    if (threadIdx.x < RELS) sh[threadIdx.x] = 0;
    __syncthreads();
    int e = blockIdx.x * blockDim.x + threadIdx.x;
    if (e < E) atomicAdd(&sh[ety[e]], 1);
    __syncthreads();
    if (threadIdx.x < RELS) atomicAdd(&g_hist[threadIdx.x], sh[threadIdx.x]);
}
__global__ void scank() {
    int off = 0, boff = 0;
    for (int r = 0; r < RELS; r++) {
        g_reloff[r] = off; g_blkoff[r] = boff; g_cursor[r] = off;
        int c = g_hist[r];
        off += c; boff += (c + 127) / 128;
    }
    g_reloff[RELS] = off; g_blkoff[RELS] = boff;
}
__global__ void permutek(const int* __restrict__ src, const int* __restrict__ dst,
                         const int* __restrict__ ety, const float* __restrict__ norm, int E) {
    __shared__ int sh[RELS], sbase[RELS];
    if (threadIdx.x < RELS) sh[threadIdx.x] = 0;
    __syncthreads();
    int e = blockIdx.x * blockDim.x + threadIdx.x;
    int r = 0, lr = 0;
    if (e < E) { r = ety[e]; lr = atomicAdd(&sh[r], 1); }
    __syncthreads();
    if (threadIdx.x < RELS) sbase[threadIdx.x] = atomicAdd(&g_cursor[threadIdx.x], sh[threadIdx.x]);
    __syncthreads();
    if (e < E) {
        int pos = sbase[r] + lr;
        g_srcp[pos] = src[e];
        g_dstp[pos] = dst[e];
        g_normp[pos] = norm[e];
    }
}

// ---------------------------------------------------------------------------
// Zero both accumulators in one launch.
// ---------------------------------------------------------------------------
__global__ void zeroall(float4* __restrict__ h4, int n4h, float4* __restrict__ o4, int n4o) {
    int i = blockIdx.x * blockDim.x + threadIdx.x;
    if (i < n4h) h4[i] = make_float4(0.f, 0.f, 0.f, 0.f);
    else if (i - n4h < n4o) o4[i - n4h] = make_float4(0.f, 0.f, 0.f, 0.f);
}

// ---------------------------------------------------------------------------
// Persistent pipelined fused kernel.
// CTA loops over a contiguous range of 128-edge tiles. Double-buffered A:
// while MMA runs on tile i, tile i+1's rows are loaded (2 register chunks),
// converted to hi/lo bf16 and stored to the alternate buffer between product
// passes. Epilogue stages into the dead current buffer (row-rotated swizzle),
// scales by norm, red.add.v4 into Out[dst]. B (W_r) reloads only when the
// relation changes.
// ---------------------------------------------------------------------------
template <int COLS, bool RELU>
__global__ __launch_bounds__(256, 1)
void rgcn_pipe(const float* __restrict__ A,
               const __nv_bfloat16* __restrict__ Whi,
               const __nv_bfloat16* __restrict__ Wlo,
               float* __restrict__ Out) {
    extern __shared__ char smem[];
    constexpr int ASUB = 16384;             // bytes per A K-subtile
    constexpr int ABUF = 65536;             // hi(2 sub) + lo(2 sub)
    constexpr int BSUB = COLS * 128;        // bytes per B K-subtile
    constexpr int BOFF = 2 * ABUF;
    constexpr int NW = (COLS == 128) ? 64 : 32;
    constexpr int NF = NW / 8;
    constexpr int CM1 = COLS - 1;
    constexpr int V4R = COLS / 4;

    const uint32_t sb = smem_u32(smem);
    const int tid = threadIdx.x;
    const int wid = tid >> 5;
    const int lane = tid & 31;
    const int wm = wid & 3;
    const int wn = wid >> 2;
    const int hf = lane >> 4;
    const int sr = lane & 15;
    const int urow = tid >> 4;
    const int ucol = tid & 15;

    const int T = __ldg(&g_blkoff[RELS]);
    const int C = (T + (int)gridDim.x - 1) / (int)gridDim.x;
    int t0 = blockIdx.x * C;
    int t1 = min(t0 + C, T);
    if (t0 >= t1) return;

    int r, e0, nE;
    tmap(t0, r, e0, nE);

    // ---- load B(r) ----
    auto loadB = [&](int rr) {
        for (int i = tid; i < COLS * 16; i += 256) {
            int n = i >> 4, u = i & 15;
            uint32_t so = (uint32_t)(u >> 3) * BSUB + SWZ128((uint32_t)(n * 128 + (u & 7) * 16));
            const size_t gi = ((size_t)rr * COLS + n) * 128 + u * 8;
            *(uint4*)(smem + BOFF + so) = *(const uint4*)(Whi + gi);
            *(uint4*)(smem + BOFF + 2 * BSUB + so) = *(const uint4*)(Wlo + gi);
        }
    };
    loadB(r);
    int rcur = r;

    // ---- full gather of first tile into buffer 0 ----
    {
#pragma unroll
        for (int it = 0; it < 8; it++) {
            int row = urow + it * 16;
            float4 v0 = make_float4(0.f, 0.f, 0.f, 0.f), v1 = v0;
            if (row < nE) {
                int s = __ldg(&g_srcp[e0 + row]);
                const float* ap = A + (size_t)s * 128 + ucol * 8;
                v0 = __ldg((const float4*)ap);
                v1 = __ldg((const float4*)(ap + 4));
            }
            cvt_store<RELU>(smem, 0u, row, ucol, v0, v1);
        }
    }
    __syncthreads();

    int buf = 0;
    for (int t = t0; t < t1; t++) {
        const bool hasNext = (t + 1 < t1);
        int rn = r, e0n = 0, nEn = 0;
        if (hasNext) tmap(t + 1, rn, e0n, nEn);

        // ---- prefetch next tile: src indices + chunk0 row data ----
        int sreg[8];
        float4 p0[4], p1[4];
        if (hasNext) {
#pragma unroll
            for (int it = 0; it < 8; it++) {
                int row = urow + it * 16;
                sreg[it] = (row < nEn) ? __ldg(&g_srcp[e0n + row]) : 0;
            }
#pragma unroll
            for (int it = 0; it < 4; it++) {
                int row = urow + it * 16;
                if (row < nEn) {
                    const float* ap = A + (size_t)sreg[it] * 128 + ucol * 8;
                    p0[it] = __ldg((const float4*)ap);
                    p1[it] = __ldg((const float4*)(ap + 4));
                } else {
                    p0[it] = make_float4(0.f, 0.f, 0.f, 0.f); p1[it] = p0[it];
                }
            }
        }

        float acc[2][NF][4];
#pragma unroll
        for (int mf = 0; mf < 2; mf++)
#pragma unroll
            for (int nf = 0; nf < NF; nf++)
#pragma unroll
                for (int j = 0; j < 4; j++) acc[mf][nf][j] = 0.f;

        const uint32_t abuf = sb + (uint32_t)buf * ABUF;
        const uint32_t nbufo = (uint32_t)(buf ^ 1) * ABUF;
        const uint32_t a_off[3] = {0u, 0u, 32768u};
        const uint32_t b_off[3] = {0u, (uint32_t)(2 * BSUB), 0u};

#pragma unroll
        for (int p = 0; p < 3; p++) {
            const uint32_t abase = abuf + a_off[p];
            const uint32_t bbase = sb + BOFF + b_off[p];
#pragma unroll
            for (int ks = 0; ks < 8; ks++) {
                const int kt = ks >> 2;
                const int kb = (ks & 3) * 32;
                uint32_t a[2][4];
#pragma unroll
                for (int mf = 0; mf < 2; mf++) {
                    int row = wm * 32 + mf * 16 + sr;
                    ldsm4(a[mf], abase + kt * ASUB + SWZ128((uint32_t)(row * 128 + kb + hf * 16)));
                }
                uint32_t b[NF][2];
#pragma unroll
                for (int nq = 0; nq < NF / 2; nq++) {
                    int n = wn * NW + nq * 16 + sr;
                    uint32_t tt[4];
                    ldsm4(tt, bbase + kt * BSUB + SWZ128((uint32_t)(n * 128 + kb + hf * 16)));
                    b[nq * 2][0] = tt[0]; b[nq * 2][1] = tt[2];
                    b[nq * 2 + 1][0] = tt[1]; b[nq * 2 + 1][1] = tt[3];
                }
#pragma unroll
                for (int mf = 0; mf < 2; mf++)
#pragma unroll
                    for (int nf = 0; nf < NF; nf++)
                        mma16816(acc[mf][nf], a[mf], b[nf]);
            }
            if (p == 0 && hasNext) {
                // convert+store chunk0 into alternate buffer; issue chunk1 LDGs
#pragma unroll
                for (int it = 0; it < 4; it++)
                    cvt_store<RELU>(smem, nbufo, urow + it * 16, ucol, p0[it], p1[it]);
#pragma unroll
                for (int it = 0; it < 4; it++) {
                    int row = urow + (it + 4) * 16;
                    if (row < nEn) {
                        const float* ap = A + (size_t)sreg[it + 4] * 128 + ucol * 8;
                        p0[it] = __ldg((const float4*)ap);
                        p1[it] = __ldg((const float4*)(ap + 4));
                    } else {
                        p0[it] = make_float4(0.f, 0.f, 0.f, 0.f); p1[it] = p0[it];
                    }
                }
            } else if (p == 1 && hasNext) {
#pragma unroll
                for (int it = 0; it < 4; it++)
                    cvt_store<RELU>(smem, nbufo, urow + (it + 4) * 16, ucol, p0[it], p1[it]);
            }
        }
        __syncthreads();   // A[buf]/B reads done; A[buf^1] fully written

        // ---- epilogue: stage into dead A[buf] (row-rotated swizzle) ----
        float* stag = (float*)(smem + (size_t)buf * ABUF);
        const int mrow = lane >> 2, mcol = (lane & 3) * 2;
#pragma unroll
        for (int mf = 0; mf < 2; mf++)
#pragma unroll
            for (int rr2 = 0; rr2 < 2; rr2++) {
                int lrow = wm * 32 + mf * 16 + mrow + rr2 * 8;
                int shift = (lrow * 4) & CM1;
#pragma unroll
                for (int nf = 0; nf < NF; nf++) {
                    int col = wn * NW + nf * 8 + mcol;
                    int scol = (col + shift) & CM1;
                    *(float2*)(stag + lrow * COLS + scol) =
                        make_float2(acc[mf][nf][rr2 * 2], acc[mf][nf][rr2 * 2 + 1]);
                }
            }
        __syncthreads();

        // ---- scale by norm, red.add.v4 into Out[dst] ----
#pragma unroll
        for (int it = 0; it < (128 * V4R) / 256; it++) {
            int idx = tid + it * 256;
            int row = idx / V4R, c4 = idx % V4R;
            if (row < nE) {
                int scol = (c4 * 4 + row * 4) & CM1;
                float4 v = *(float4*)(stag + row * COLS + scol);
                float nm = __ldg(&g_normp[e0 + row]);
                int d = __ldg(&g_dstp[e0 + row]);
                v.x *= nm; v.y *= nm; v.z *= nm; v.w *= nm;
                float* o = Out + (size_t)d * COLS + c4 * 4;
                asm volatile("red.global.add.v4.f32 [%0], {%1, %2, %3, %4};"
                             :: "l"(o), "f"(v.x), "f"(v.y), "f"(v.z), "f"(v.w) : "memory");
            }
        }
        __syncthreads();   // staging consumed before next tile's converts reuse it

        buf ^= 1;
        if (hasNext) {
            r = rn; e0 = e0n; nE = nEn;
            if (r != rcur) {
                loadB(r);
                rcur = r;
                __syncthreads();
            }
        }
    }
}

// ---------------------------------------------------------------------------
// Launch. Layer-1 pipe kernel is launch #6 (ncu -s 5 -c 1 captures it).
// ---------------------------------------------------------------------------
extern "C" void kernel_launch(void* const* d_in, const int* in_sizes, int n_in,
                              void* d_out, int out_size) {
    const float* feat = (const float*)d_in[0];
    const float* norm = (const float*)d_in[1];
    const float* W1   = (const float*)d_in[2];
    const float* W2   = (const float*)d_in[3];
    const int*   src  = (const int*)d_in[4];
    const int*   dst  = (const int*)d_in[5];
    const int*   ety  = (const int*)d_in[6];
    float* out = (float*)d_out;

    const int N = in_sizes[0] / INDIM;   // 50000
    const int E = in_sizes[4];           // 800000

    float* hp;
    __nv_bfloat16 *w1hip, *w1lop, *w2hip, *w2lop;
    cudaGetSymbolAddress((void**)&hp,    g_h);
    cudaGetSymbolAddress((void**)&w1hip, g_w1hi);
    cudaGetSymbolAddress((void**)&w1lop, g_w1lo);
    cudaGetSymbolAddress((void**)&w2hip, g_w2hi);
    cudaGetSymbolAddress((void**)&w2lop, g_w2lo);

    constexpr int SM1 = 2 * 65536 + 4 * 128 * 128;  // 196608 B
    constexpr int SM2 = 2 * 65536 + 4 * 64 * 128;   // 163840 B
    cudaFuncSetAttribute(rgcn_pipe<128, false>,
                         cudaFuncAttributeMaxDynamicSharedMemorySize, SM1);
    cudaFuncSetAttribute(rgcn_pipe<64, true>,
                         cudaFuncAttributeMaxDynamicSharedMemorySize, SM2);

    // 1. weight split (+hist zero)
    splitWall<<<1024, 256>>>(W1, W2, w1hip, w1lop, w2hip, w2lop);
    // 2-4. edge bucket sort
    const int eb = (E + 255) / 256;
    histk<<<eb, 256>>>(ety, E);
    scank<<<1, 1>>>();
    permutek<<<eb, 256>>>(src, dst, ety, norm, E);
    // 5. zero accumulators
    {
        int n4h = N * HDIM / 4, n4o = N * ODIM / 4;
        zeroall<<<(n4h + n4o + 255) / 256, 256>>>((float4*)hp, n4h, (float4*)out, n4o);
    }
    // 6. layer 1 (persistent, pipelined)
    rgcn_pipe<128, false><<<148, 256, SM1>>>(feat, w1hip, w1lop, hp);
    // 7. layer 2
    rgcn_pipe<64, true><<<148, 256, SM2>>>(hp, w2hip, w2lop, out);
}